// round 17
// baseline (speedup 1.0000x reference)
#include <cuda_runtime.h>
#include <cuda_fp16.h>
#include <stdint.h>

// ============================================================================
// Llama4TextExperts grouped GEMM + SwiGLU, fp32 in/out.
// Single-term fp16 HMMA, cp.async multistage (no producer warps):
// 256 thr = 8 consumer warps (2m x 4n @64x64, CTA 128x256), 2 warps/SMSP.
// Kc=128, NST=2 (96KB stages) -> half the chunk-overhead instances of R16.
//   prepass: X, Wgu, Wd fp32 -> fp16 globals (one merged kernel)
//   GEMM1: Xh @ Wguh -> SwiGLU -> g_scr (fp16)
//   GEMM2: g_scr @ Wdh -> out fp32
// ============================================================================

#define NSM 148
#define NST 2
#define STG_B 98304                       // A 32KB @0, B 64KB @32K
#define SMEM_BYTES (1024 + NST * STG_B)

static __device__ __half g_scr[(size_t)8 * 1024 * 4096];    // 64 MB
static __device__ __half Xh[(size_t)8192 * 2048];           // 32 MB
static __device__ __half Wguh[(size_t)8 * 2048 * 8192];     // 256 MB
static __device__ __half Wdh[(size_t)8 * 4096 * 2048];      // 128 MB

// ---------------- helpers ----------------
__device__ __forceinline__ uint32_t s2u(const void* p) {
    uint32_t a;
    asm("{ .reg .u64 t; cvta.to.shared.u64 t, %1; cvt.u32.u64 %0, t; }" : "=r"(a) : "l"(p));
    return a;
}
__device__ __forceinline__ uint32_t swzB(uint32_t o) { return o ^ ((o >> 4) & 0x70); }  // 256B rows
__device__ __forceinline__ uint32_t swzC(uint32_t o) { return o ^ ((o >> 5) & 0x70); }  // 512B rows

__device__ __forceinline__ uint32_t pkh(float a, float b) {
    __half2 h = __floats2half2_rn(a, b);
    return *reinterpret_cast<uint32_t*>(&h);
}
__device__ __forceinline__ float silu_mul(float g, float u) {
    return u * __fdividef(g, 1.0f + __expf(-g));
}
__device__ __forceinline__ void cpa16(uint32_t dst, const void* src) {
    asm volatile("cp.async.cg.shared.global [%0], [%1], 16;" :: "r"(dst), "l"(src) : "memory");
}
__device__ __forceinline__ void ldsm4(uint32_t* r, uint32_t addr) {
    asm volatile("ldmatrix.sync.aligned.m8n8.x4.shared.b16 {%0,%1,%2,%3}, [%4];"
                 : "=r"(r[0]), "=r"(r[1]), "=r"(r[2]), "=r"(r[3]) : "r"(addr));
}
__device__ __forceinline__ void ldsm4t(uint32_t* r, uint32_t addr) {
    asm volatile("ldmatrix.sync.aligned.m8n8.x4.trans.shared.b16 {%0,%1,%2,%3}, [%4];"
                 : "=r"(r[0]), "=r"(r[1]), "=r"(r[2]), "=r"(r[3]) : "r"(addr));
}
__device__ __forceinline__ void mma16816(float* c, const uint32_t* a, const uint32_t* b) {
    asm volatile(
        "mma.sync.aligned.m16n8k16.row.col.f32.f16.f16.f32 "
        "{%0,%1,%2,%3}, {%4,%5,%6,%7}, {%8,%9}, {%0,%1,%2,%3};"
        : "+f"(c[0]), "+f"(c[1]), "+f"(c[2]), "+f"(c[3])
        : "r"(a[0]), "r"(a[1]), "r"(a[2]), "r"(a[3]), "r"(b[0]), "r"(b[1]));
}

// ---------------- merged prepass: fp32 -> fp16 (3 regions, 1 launch) --------
__global__ __launch_bounds__(256) void cvt3_ker(const float4* __restrict__ s1, uint2* d1, int n1,
                                                const float4* __restrict__ s2, uint2* d2, int n2,
                                                const float4* __restrict__ s3, uint2* d3, int n3) {
    const int stride = gridDim.x * 256;
    int i = blockIdx.x * 256 + threadIdx.x;
    const int ntot = n1 + n2 + n3;
    for (; i < ntot; i += stride) {
        const float4* s;
        uint2* d;
        int j = i;
        if (j < n1) { s = s1; d = d1; }
        else if ((j -= n1) < n2) { s = s2; d = d2; }
        else { j -= n2; s = s3; d = d3; }
        float4 v = s[j];
        d[j] = make_uint2(pkh(v.x, v.y), pkh(v.z, v.w));
    }
}

// ============================================================================
//   KDIM : 2048 / 4096.  NTILE: 256-col n-tiles per expert (32 / 8).
//   MODE2=false: GEMM1. A = Xh (w2048). B = Wguh (w8192), gate/up paired at
//                32-col granularity per warp: tile col n' -> w=n'>>6,
//                kind=(n'>>5)&1, pair=n'&31; col = nt*128+w*32+pair+kind*4096.
//                Epilogue: register SwiGLU -> g_scr fp16.
//   MODE2=true : GEMM2. A = g_scr (w4096). B = Wdh (w2048). C fp32 (w2048).
// Stage (96KB): A@0 (128r x 256B, swzB), B@32K (128 k-rows x 512B, swzC).
// 8 warps, 2(m) x 4(n), 64x64 tiles; every warp issues cp.async too.
// ============================================================================
template <int KDIM, int NTILE, bool MODE2>
__global__ __launch_bounds__(256, 1) void gemm_ker(float* __restrict__ C_) {
    extern __shared__ char smem[];
    constexpr int NC   = KDIM / 128;            // 16 / 32
    constexpr int NWB  = MODE2 ? 2048 : 8192;   // B row width
    constexpr int AW   = MODE2 ? 4096 : 2048;   // A row width
    constexpr int PERE = 8 * NTILE;
    constexpr int TOT  = 8 * PERE;

    const int tid  = threadIdx.x;
    const int wid  = tid >> 5;
    const int lane = tid & 31;

    const uint32_t smbase  = s2u(smem);
    const uint32_t tiles_u = (smbase + 1023) & ~1023u;

    // ---- loader mapping (all threads) ----
    const int a_u  = tid & 15;           // 16B unit within 256B A row
    const int a_r0 = tid >> 4;           // 0..15 (stride 16, 8 iters)
    const int b_u  = tid & 31;           // 16B unit within 512B B row
    const int b_k0 = tid >> 5;           // 0..7 (stride 8, 16 iters)
    // gate/up pairing (GEMM1): nt-independent part of the B column
    int bloc;
    if (MODE2) bloc = b_u * 8;
    else {
        const int np = b_u * 8;
        bloc = (np >> 6) * 32 + (np & 31) + ((np >> 5) & 1) * 4096;
    }

    // ---- consumer fragment addressing ----
    const int wm = wid >> 2;             // 0..1  (64 m-rows each)
    const int wn = wid & 3;              // 0..3  (64 n-cols each)
    const int lane15 = lane & 15;
    const int seg    = (lane >> 4) * 16;
    const uint32_t lxor = (uint32_t)((lane & 7) << 4);
    uint32_t a_row[4], b_colx[4];
    #pragma unroll
    for (int st = 0; st < 4; st++)
        a_row[st] = (uint32_t)((wm * 64 + st * 16 + lane15) * 256);
    #pragma unroll
    for (int ng = 0; ng < 4; ng++)
        b_colx[ng] = (uint32_t)(((wn * 64 + ng * 16) * 2 + seg)) ^ lxor;
    const uint32_t b_rowb = (uint32_t)(lane15 * 512);

    for (int t = blockIdx.x; t < TOT; t += gridDim.x) {
        const int e   = t / PERE;
        const int r   = t % PERE;
        const int sup = r >> 6;
        const int r2  = r & 63;
        const int mt  = r2 & 7;
        const int nt  = MODE2 ? (r2 >> 3) : (sup * 8 + (r2 >> 3));

        const __half* Asrc = (MODE2 ? g_scr : Xh)
                           + (size_t)(e * 1024 + mt * 128) * AW;
        const __half* Bsrc = (MODE2 ? Wdh : Wguh)
                           + (size_t)e * KDIM * NWB
                           + (size_t)nt * (MODE2 ? 256 : 128) + bloc;

        // ---- cp.async issue for one 128-k chunk ----
        auto issue = [&](int c) {
            const uint32_t sb = tiles_u + (c & (NST - 1)) * STG_B;
            const int kb = c * 128;
            #pragma unroll
            for (int p = 0; p < 8; p++) {
                const int row = a_r0 + p * 16;
                cpa16(sb + swzB((uint32_t)(row * 256 + a_u * 16)),
                      Asrc + (size_t)row * AW + kb + a_u * 8);
            }
            #pragma unroll
            for (int p = 0; p < 16; p++) {
                const int k = b_k0 + p * 8;
                cpa16(sb + 32768 + swzC((uint32_t)(k * 512 + b_u * 16)),
                      Bsrc + (size_t)(kb + k) * NWB);
            }
            asm volatile("cp.async.commit_group;" ::: "memory");
        };

        // prologue: chunk 0
        issue(0);

        float acc[4][8][4];
        #pragma unroll
        for (int st = 0; st < 4; st++)
            #pragma unroll
            for (int j = 0; j < 8; j++)
                #pragma unroll
                for (int i = 0; i < 4; i++) acc[st][j][i] = 0.0f;

        for (int c = 0; c < NC; c++) {
            asm volatile("cp.async.wait_group 0;" ::: "memory");
            __syncthreads();
            if (c + 1 < NC) issue(c + 1);

            const uint32_t AhU = tiles_u + (c & (NST - 1)) * STG_B;
            const uint32_t BhU = AhU + 32768;
            #pragma unroll
            for (int ks = 0; ks < 8; ks++) {
                const uint32_t acol = (uint32_t)(ks * 32 + seg) ^ lxor;
                const uint32_t brow = b_rowb + (uint32_t)(ks * 8192);
                uint32_t ah[4][4], bh[4][4];
                #pragma unroll
                for (int st = 0; st < 4; st++)
                    ldsm4(ah[st], AhU + a_row[st] + acol);
                #pragma unroll
                for (int ng = 0; ng < 4; ng++)
                    ldsm4t(bh[ng], BhU + brow + b_colx[ng]);
                #pragma unroll
                for (int st = 0; st < 4; st++)
                    #pragma unroll
                    for (int ng = 0; ng < 4; ng++)
                        #pragma unroll
                        for (int hf = 0; hf < 2; hf++)
                            mma16816(acc[st][ng * 2 + hf], ah[st], &bh[ng][2 * hf]);
            }
        }

        // ----------------- epilogue (register-only) --------
        if (MODE2) {
            float* Ce = C_ + (size_t)(e * 1024 + mt * 128) * 2048
                      + (size_t)nt * 256 + wn * 64;
            #pragma unroll
            for (int st = 0; st < 4; st++)
                #pragma unroll
                for (int j = 0; j < 8; j++) {
                    const int r0 = wm * 64 + st * 16 + (lane >> 2);
                    const int cc = j * 8 + (lane & 3) * 2;
                    float2 v0; v0.x = acc[st][j][0]; v0.y = acc[st][j][1];
                    float2 v1; v1.x = acc[st][j][2]; v1.y = acc[st][j][3];
                    *reinterpret_cast<float2*>(Ce + (size_t)r0 * 2048 + cc) = v0;
                    *reinterpret_cast<float2*>(Ce + (size_t)(r0 + 8) * 2048 + cc) = v1;
                }
        } else {
            // warp tile cols wn*64..+63: gate = local 0..31 (j<4),
            // up = local 32..63 (j+4). Register SwiGLU -> g_scr.
            __half* scrb = g_scr + (size_t)(e * 1024 + mt * 128) * 4096
                         + (size_t)nt * 128 + wn * 32;
            #pragma unroll
            for (int st = 0; st < 4; st++)
                #pragma unroll
                for (int j = 0; j < 4; j++) {
                    const int r0 = wm * 64 + st * 16 + (lane >> 2);
                    const int cc = j * 8 + (lane & 3) * 2;
                    const float i0 = silu_mul(acc[st][j][0], acc[st][j + 4][0]);
                    const float i1 = silu_mul(acc[st][j][1], acc[st][j + 4][1]);
                    const float i2 = silu_mul(acc[st][j][2], acc[st][j + 4][2]);
                    const float i3 = silu_mul(acc[st][j][3], acc[st][j + 4][3]);
                    *reinterpret_cast<uint32_t*>(scrb + (size_t)r0 * 4096 + cc) = pkh(i0, i1);
                    *reinterpret_cast<uint32_t*>(scrb + (size_t)(r0 + 8) * 4096 + cc) = pkh(i2, i3);
                }
        }
        // no trailing sync needed: NC is even, so stage 0 is last READ at
        // chunk NC-2; every warp passed the chunk NC-1 __syncthreads before
        // the next tile's prologue writes stage 0.
    }
}

// ============================================================================
extern "C" void kernel_launch(void* const* d_in, const int* in_sizes, int n_in,
                              void* d_out, int out_size) {
    const float* X   = (const float*)d_in[0];   // (8192, 2048)
    const float* Wgu = (const float*)d_in[1];   // (8, 2048, 8192)
    const float* Wd  = (const float*)d_in[2];   // (8, 4096, 2048)
    float* out = (float*)d_out;                 // (8192, 2048)

    __half *xh_p, *wguh_p, *wdh_p;
    cudaGetSymbolAddress((void**)&xh_p, Xh);
    cudaGetSymbolAddress((void**)&wguh_p, Wguh);
    cudaGetSymbolAddress((void**)&wdh_p, Wdh);

    cudaFuncSetAttribute(gemm_ker<2048, 32, false>,
                         cudaFuncAttributeMaxDynamicSharedMemorySize, SMEM_BYTES);
    cudaFuncSetAttribute(gemm_ker<4096, 8, true>,
                         cudaFuncAttributeMaxDynamicSharedMemorySize, SMEM_BYTES);

    // merged prepass conversion (X, Wgu, Wd -> fp16), one launch
    cvt3_ker<<<8192, 256>>>((const float4*)X,   (uint2*)xh_p,   8192 * 2048 / 4,
                            (const float4*)Wgu, (uint2*)wguh_p, 8 * 2048 * 8192 / 4,
                            (const float4*)Wd,  (uint2*)wdh_p,  8 * 4096 * 2048 / 4);

    gemm_ker<2048, 32, false><<<NSM, 256, SMEM_BYTES>>>(nullptr);
    gemm_ker<4096, 8, true><<<NSM, 256, SMEM_BYTES>>>(out);
}